// round 6
// baseline (speedup 1.0000x reference)
#include <cuda_runtime.h>

// y = s1 * FWHT( g * FWHT( s2 * x ) ) per token, D = 4096 = 2^12.
// 16 floats/thread = 4 logical bits in registers; butterflies in registers.
// Warp w owns elements with i9-11 = w (512-float private smem region), so
// X1/X4 are warp-local (syncwarp only). i8 is one shfl_xor(16) stage.
// Only X2/X3 cross warps -> 3 __syncthreads per token.
//
// map A (X1/X4): A(i) = w<<9 | i4_7<<5 | i8<<4 | (i0_3 ^ i4_7)
//   X1 write lanes vary (i4-7,i8): bank = i8<<4 | (c ^ i4_7)  -> bijective
//   X1 read  lanes vary (i0-3,i8): bank = i8<<4 | (i0_3 ^ c) -> bijective
// map B (X2/X3): B(i) = i0_3 | i8<<4 | i4<<5 | i5_7<<6 | i9_11<<9
//   both sides' lanes vary (i0-3, i8) = bank bits -> bijective
// Round trips verified symbolically (write addr == read addr per element).

#define DDIM 4096
#define TPC  4

__device__ __forceinline__ float softplus_f(float x) {
    return fmaxf(x, 0.0f) + log1pf(expf(-fabsf(x)));
}

// FWHT over reg bits 0..3 (16 regs).
__device__ __forceinline__ void bfly4(float v[16]) {
#pragma unroll
    for (int b = 1; b < 16; b <<= 1) {
#pragma unroll
        for (int r = 0; r < 16; r++) {
            if (!(r & b)) {
                float a = v[r], c = v[r | b];
                v[r]     = a + c;
                v[r | b] = a - c;
            }
        }
    }
}

// FWHT over reg bits 0..2 only (bit 3 is a passenger).
__device__ __forceinline__ void bfly3(float v[16]) {
#pragma unroll
    for (int b = 1; b < 8; b <<= 1) {
#pragma unroll
        for (int r = 0; r < 16; r++) {
            if (!(r & b)) {
                float a = v[r], c = v[r | b];
                v[r]     = a + c;
                v[r | b] = a - c;
            }
        }
    }
}

__global__ void __launch_bounds__(256, 4)
whvi_kernel(const float* __restrict__ x,
            const float* __restrict__ s1,
            const float* __restrict__ s2,
            const float* __restrict__ g_mu,
            const float* __restrict__ g_rho,
            const float* __restrict__ eps,
            float* __restrict__ out,
            int n_tokens)
{
    __shared__ float sh[DDIM];     // exchange buffer (maps A and B, phase-guarded)
    __shared__ float gbuf[DDIM];   // g_tilde at map-B addresses

    const int t = threadIdx.x;     // 256 threads
    const int l = t & 31;
    const int w = t >> 5;          // 3 bits = i9-11 (warp-private region)
    const int m = l & 15;
    const int h = l >> 4;

    // Base addresses (per-r offsets below are immediates or one LOP3).
    const int x1w = (w << 9) | (m << 5) | (h << 4);  // L0 side of map A
    const int x1r = (w << 9) | (h << 4);             // L1 side of map A
    const int x2w = m | (h << 4) | (w << 9);         // L1f side of map B (warp-private)
    const int x2r = m | (h << 4) | (w << 6);         // L2 side of map B (cross-warp)

    // g_tilde once per CTA, stored at map-B addresses (conflict-free, matches
    // the L2-layout read below). Visibility ordered by token-0's X2 barrier.
#pragma unroll
    for (int r = 0; r < 16; r++) {
        const int i = m | ((r >> 3) << 4) | (w << 5) | (h << 8) | ((r & 7) << 9);
        gbuf[x2r + ((r & 7) << 9) + ((r >> 3) << 5)] =
            g_mu[i] + softplus_f(g_rho[i]) * eps[i];
    }

    const float sgn8 = (l & 16) ? -1.0f : 1.0f;
    const int tok0 = blockIdx.x * TPC;

    for (int it = 0; it < TPC; it++) {
        const int tok = tok0 + it;
        if (tok >= n_tokens) break;

        float v[16];
        // ---- load x (float4, coalesced), * s2 ----  L0: i = t<<4 | r
        const float4* __restrict__ xr  = (const float4*)(x  + (size_t)tok * DDIM + (t << 4));
        const float4* __restrict__ s2r = (const float4*)(s2 + (t << 4));
#pragma unroll
        for (int q = 0; q < 4; q++) {
            float4 a = xr[q], b = s2r[q];
            v[4*q+0] = a.x * b.x;  v[4*q+1] = a.y * b.y;
            v[4*q+2] = a.z * b.z;  v[4*q+3] = a.w * b.w;
        }

        bfly4(v);                                   // FWHT1 i0-3

        // ---- X1: warp-local, L0 -> L1 (map A) ----
        __syncwarp();                               // WAR vs prev token X4 read
#pragma unroll
        for (int r = 0; r < 16; r++) sh[x1w | (r ^ m)] = v[r];
        __syncwarp();
#pragma unroll
        for (int r = 0; r < 16; r++) v[r] = sh[x1r + (r << 5) + (m ^ r)];

        bfly4(v);                                   // FWHT1 i4-7

        // ---- FWHT1 i8 via shuffle (lane bit 4) ----
#pragma unroll
        for (int r = 0; r < 16; r++) {
            float p = __shfl_xor_sync(0xffffffffu, v[r], 16);
            v[r] = fmaf(sgn8, v[r], p);
        }

        // ---- X2: L1f -> L2 (map B); write warp-private, read crosses ----
        __syncwarp();
#pragma unroll
        for (int r = 0; r < 16; r++) sh[x2w + (r << 5)] = v[r];
        __syncthreads();
#pragma unroll
        for (int r = 0; r < 16; r++)
            v[r] = sh[x2r + ((r & 7) << 9) + ((r >> 3) << 5)];

        bfly3(v);                                   // FWHT1 i9-11
#pragma unroll
        for (int r = 0; r < 16; r++)                // * g_tilde (map-B, conflict-free)
            v[r] *= gbuf[x2r + ((r & 7) << 9) + ((r >> 3) << 5)];
        bfly3(v);                                   // FWHT2 i9-11

        // ---- X3: L2 -> L1f (map B reversed) ----
        __syncthreads();                            // WAR: everyone done X2-reads
#pragma unroll
        for (int r = 0; r < 16; r++)
            sh[x2r + ((r & 7) << 9) + ((r >> 3) << 5)] = v[r];
        __syncthreads();
#pragma unroll
        for (int r = 0; r < 16; r++) v[r] = sh[x2w + (r << 5)];

        // ---- FWHT2 i8 via shuffle ----
#pragma unroll
        for (int r = 0; r < 16; r++) {
            float p = __shfl_xor_sync(0xffffffffu, v[r], 16);
            v[r] = fmaf(sgn8, v[r], p);
        }

        bfly4(v);                                   // FWHT2 i4-7

        // ---- X4: warp-local, L1 -> L0 (map A reversed) ----
        __syncwarp();
#pragma unroll
        for (int r = 0; r < 16; r++) sh[x1r + (r << 5) + (m ^ r)] = v[r];
        __syncwarp();
#pragma unroll
        for (int r = 0; r < 16; r++) v[r] = sh[x1w | (r ^ m)];

        bfly4(v);                                   // FWHT2 i0-3

        // ---- * s1, store (float4, coalesced) ----
        const float4* __restrict__ s1r = (const float4*)(s1 + (t << 4));
        float4* __restrict__ orow = (float4*)(out + (size_t)tok * DDIM + (t << 4));
#pragma unroll
        for (int q = 0; q < 4; q++) {
            float4 b = s1r[q];
            orow[q] = make_float4(v[4*q+0] * b.x, v[4*q+1] * b.y,
                                  v[4*q+2] * b.z, v[4*q+3] * b.w);
        }
    }
}

extern "C" void kernel_launch(void* const* d_in, const int* in_sizes, int n_in,
                              void* d_out, int out_size)
{
    const float* x     = (const float*)d_in[0];
    const float* s1    = (const float*)d_in[1];
    const float* s2    = (const float*)d_in[2];
    const float* g_mu  = (const float*)d_in[3];
    const float* g_rho = (const float*)d_in[4];
    const float* eps   = (const float*)d_in[5];
    // d_in[6] = H, unused (FWHT computes it implicitly)

    float* out = (float*)d_out;
    const int n_tokens = in_sizes[0] / DDIM;
    const int grid = (n_tokens + TPC - 1) / TPC;

    whvi_kernel<<<grid, 256>>>(x, s1, s2, g_mu, g_rho, eps, out, n_tokens);
}

// round 7
// speedup vs baseline: 1.3155x; 1.3155x over previous
#include <cuda_runtime.h>

// y = s1 * FWHT( g * FWHT( s2 * x ) ) per token, D = 4096.
// R0 dataflow (proven correct, 90.6us) with parameters moved out of registers:
// g_tilde in linear smem (conflict-free reads), s1/s2 re-read per token from
// global (L1-resident). Register count drops ~80 -> ~50 => 4 CTAs/SM.

#define DDIM 4096
#define TPC  8

__device__ __forceinline__ float softplus_f(float x) {
    return fmaxf(x, 0.0f) + log1pf(expf(-fabsf(x)));
}

__global__ void __launch_bounds__(256, 4)
whvi_kernel(const float* __restrict__ x,
            const float* __restrict__ s1,
            const float* __restrict__ s2,
            const float* __restrict__ g_mu,
            const float* __restrict__ g_rho,
            const float* __restrict__ eps,
            float* __restrict__ out,
            int n_tokens)
{
    __shared__ float sh[DDIM];     // exchange buffer
    __shared__ float gbuf[DDIM];   // g_tilde, linear

    const int t = threadIdx.x;     // 0..255
    const int l = t & 31;          // lane  = element bits 0..4
    const int w = t >> 5;          // warp  = element bits 5..7 (in L1 layout)

    // ---- g_tilde once per CTA (linear layout) ----
#pragma unroll
    for (int r = 0; r < 16; r++) {
        const int i = t + (r << 8);
        gbuf[i] = g_mu[i] + softplus_f(g_rho[i]) * eps[i];
    }
    __syncthreads();

    const int tok0 = blockIdx.x * TPC;

    for (int it = 0; it < TPC; it++) {
        const int tok = tok0 + it;
        if (tok >= n_tokens) break;
        const float* __restrict__ xr = x + (size_t)tok * DDIM;

        // ---- load + scale by s2 (L0: v[r] = elem t + 256r) ----
        float v[16];
#pragma unroll
        for (int r = 0; r < 16; r++)
            v[r] = xr[t + 256 * r] * s2[t + 256 * r];

        // ---- FWHT1: register stages (bits 8..11) ----
#pragma unroll
        for (int b = 1; b < 16; b <<= 1)
#pragma unroll
            for (int r = 0; r < 16; r++)
                if (!(r & b)) {
                    float a = v[r], c = v[r | b];
                    v[r] = a + c;  v[r | b] = a - c;
                }

        // ---- FWHT1: shuffle stages (bits 0..4) ----
#pragma unroll
        for (int s = 0; s < 5; s++) {
            const int m = 1 << s;
            const float sgn = (l & m) ? -1.0f : 1.0f;
#pragma unroll
            for (int r = 0; r < 16; r++) {
                float pv = __shfl_xor_sync(0xffffffffu, v[r], m);
                v[r] = fmaf(sgn, v[r], pv);
            }
        }

        // ---- exchange 1: L0 -> L1 ----
        __syncthreads();
#pragma unroll
        for (int r = 0; r < 16; r++) sh[t + 256 * r] = v[r];
        __syncthreads();

        float u[2][8];
#pragma unroll
        for (int p = 0; p < 2; p++)
#pragma unroll
            for (int k = 0; k < 8; k++)
                u[p][k] = sh[l + (k << 5) + (((w << 1) + p) << 8)];

        // ---- FWHT1 bits 5..7, * g_tilde, FWHT2 bits 5..8 ----
#pragma unroll
        for (int b = 1; b < 8; b <<= 1)
#pragma unroll
            for (int p = 0; p < 2; p++)
#pragma unroll
                for (int k = 0; k < 8; k++)
                    if (!(k & b)) {
                        float a = u[p][k], c = u[p][k | b];
                        u[p][k] = a + c;  u[p][k | b] = a - c;
                    }

#pragma unroll
        for (int p = 0; p < 2; p++)
#pragma unroll
            for (int k = 0; k < 8; k++)
                u[p][k] *= gbuf[l + (k << 5) + (((w << 1) + p) << 8)];

#pragma unroll
        for (int b = 1; b < 8; b <<= 1)
#pragma unroll
            for (int p = 0; p < 2; p++)
#pragma unroll
                for (int k = 0; k < 8; k++)
                    if (!(k & b)) {
                        float a = u[p][k], c = u[p][k | b];
                        u[p][k] = a + c;  u[p][k | b] = a - c;
                    }

#pragma unroll
        for (int k = 0; k < 8; k++) {       // bit 8 (p)
            float a = u[0][k], c = u[1][k];
            u[0][k] = a + c;  u[1][k] = a - c;
        }

        // ---- FWHT2: shuffle stages (bits 0..4) ----
#pragma unroll
        for (int s = 0; s < 5; s++) {
            const int m = 1 << s;
            const float sgn = (l & m) ? -1.0f : 1.0f;
#pragma unroll
            for (int p = 0; p < 2; p++)
#pragma unroll
                for (int k = 0; k < 8; k++) {
                    float pv = __shfl_xor_sync(0xffffffffu, u[p][k], m);
                    u[p][k] = fmaf(sgn, u[p][k], pv);
                }
        }

        // ---- exchange 2: L1 -> L2 ----
        __syncthreads();
#pragma unroll
        for (int p = 0; p < 2; p++)
#pragma unroll
            for (int k = 0; k < 8; k++)
                sh[l + (k << 5) + (((w << 1) + p) << 8)] = u[p][k];
        __syncthreads();

        float z[2][8];
#pragma unroll
        for (int p = 0; p < 2; p++)
#pragma unroll
            for (int j = 0; j < 8; j++)
                z[p][j] = sh[t + (p << 8) + (j << 9)];

        // ---- FWHT2: register stages (bits 9..11) ----
#pragma unroll
        for (int b = 1; b < 8; b <<= 1)
#pragma unroll
            for (int p = 0; p < 2; p++)
#pragma unroll
                for (int j = 0; j < 8; j++)
                    if (!(j & b)) {
                        float a = z[p][j], c = z[p][j | b];
                        z[p][j] = a + c;  z[p][j | b] = a - c;
                    }

        // ---- * s1, store (coalesced) ----
        float* __restrict__ orow = out + (size_t)tok * DDIM;
#pragma unroll
        for (int p = 0; p < 2; p++)
#pragma unroll
            for (int j = 0; j < 8; j++) {
                const int i = t + (p << 8) + (j << 9);
                orow[i] = z[p][j] * s1[i];
            }
    }
}

extern "C" void kernel_launch(void* const* d_in, const int* in_sizes, int n_in,
                              void* d_out, int out_size)
{
    const float* x     = (const float*)d_in[0];
    const float* s1    = (const float*)d_in[1];
    const float* s2    = (const float*)d_in[2];
    const float* g_mu  = (const float*)d_in[3];
    const float* g_rho = (const float*)d_in[4];
    const float* eps   = (const float*)d_in[5];
    // d_in[6] = H, unused

    float* out = (float*)d_out;
    const int n_tokens = in_sizes[0] / DDIM;
    const int grid = (n_tokens + TPC - 1) / TPC;

    whvi_kernel<<<grid, 256>>>(x, s1, s2, g_mu, g_rho, eps, out, n_tokens);
}